// round 1
// baseline (speedup 1.0000x reference)
#include <cuda_runtime.h>
#include <math.h>

#define VOCAB  50257
#define HDIM   256
#define FDIM   512
#define NBATCH 16
#define SEQT   4096
#define TCAND  4093   // SEQT - 3
#define MSEL   512

// ---------------- device scratch (static allocation; no cudaMalloc) ----------------
__device__ float g_t1[(size_t)VOCAB * FDIM];      // relu(embed@W1+b1), ~103 MB
__device__ float g_hidden[(size_t)VOCAB * HDIM];  // LN(h+ff) per vocab row, ~51.5 MB
__device__ float g_score[VOCAB];                  // gate score per vocab row
__device__ int   g_mem_tok[NBATCH * MSEL];        // selected token ids per batch
__device__ float g_ctx[NBATCH * HDIM];            // attention context per batch

__device__ __forceinline__ float wred_sum(float v) {
#pragma unroll
  for (int o = 16; o > 0; o >>= 1) v += __shfl_xor_sync(0xffffffffu, v, o);
  return v;
}

// ---------------- Pass 1: t1 = relu(embed @ W1 + b1), (V,256)x(256,512) ----------------
// BM=128, BN=128, BK=16, 256 threads, 8x8 micro-tile
__global__ __launch_bounds__(256) void k_ffn1(const float* __restrict__ E,
                                              const float* __restrict__ W1,
                                              const float* __restrict__ b1) {
  __shared__ __align__(16) float As[16][132];  // [k][row], padded
  __shared__ __align__(16) float Bs[16][132];  // [k][col], padded
  const int tid = threadIdx.x;
  const int tx = tid & 15, ty = tid >> 4;
  const int row0 = blockIdx.x * 128;
  const int col0 = blockIdx.y * 128;

  float acc[8][8];
#pragma unroll
  for (int i = 0; i < 8; i++)
#pragma unroll
    for (int j = 0; j < 8; j++) acc[i][j] = 0.f;

  for (int k0 = 0; k0 < HDIM; k0 += 16) {
    // A tile: 128 rows x 16 k (512 float4, 2 per thread), stored transposed
#pragma unroll
    for (int l = 0; l < 2; l++) {
      int f = tid + l * 256;
      int r = f >> 2;
      int kq = (f & 3) << 2;
      int grow = row0 + r;
      float4 v = make_float4(0.f, 0.f, 0.f, 0.f);
      if (grow < VOCAB) v = *(const float4*)(E + (size_t)grow * HDIM + k0 + kq);
      As[kq + 0][r] = v.x; As[kq + 1][r] = v.y; As[kq + 2][r] = v.z; As[kq + 3][r] = v.w;
    }
    // B tile: 16 k x 128 cols
#pragma unroll
    for (int l = 0; l < 2; l++) {
      int f = tid + l * 256;
      int r = f >> 5;
      int nq = (f & 31) << 2;
      *(float4*)&Bs[r][nq] = *(const float4*)(W1 + (size_t)(k0 + r) * FDIM + col0 + nq);
    }
    __syncthreads();
#pragma unroll
    for (int k = 0; k < 16; k++) {
      float a[8], bv[8];
      *(float4*)&a[0]  = *(const float4*)&As[k][ty * 8];
      *(float4*)&a[4]  = *(const float4*)&As[k][ty * 8 + 4];
      *(float4*)&bv[0] = *(const float4*)&Bs[k][tx * 8];
      *(float4*)&bv[4] = *(const float4*)&Bs[k][tx * 8 + 4];
#pragma unroll
      for (int i = 0; i < 8; i++)
#pragma unroll
        for (int j = 0; j < 8; j++) acc[i][j] = fmaf(a[i], bv[j], acc[i][j]);
    }
    __syncthreads();
  }

  float bias[8];
  *(float4*)&bias[0] = *(const float4*)(b1 + col0 + tx * 8);
  *(float4*)&bias[4] = *(const float4*)(b1 + col0 + tx * 8 + 4);
#pragma unroll
  for (int i = 0; i < 8; i++) {
    int grow = row0 + ty * 8 + i;
    if (grow < VOCAB) {
      float o[8];
#pragma unroll
      for (int j = 0; j < 8; j++) o[j] = fmaxf(acc[i][j] + bias[j], 0.f);
      *(float4*)(g_t1 + (size_t)grow * FDIM + col0 + tx * 8)     = *(float4*)&o[0];
      *(float4*)(g_t1 + (size_t)grow * FDIM + col0 + tx * 8 + 4) = *(float4*)&o[4];
    }
  }
}

// ---------------- Pass 2: ff = t1 @ W2 + b2; x = h + ff; LN; hidden + gate score ----------------
// BM=64, BN=256 (full row so LN can fuse), BK=16, 256 threads, 8x8 micro-tile.
// Warp ty owns rows [ty*8, ty*8+8); its 32 lanes cover all 256 columns -> per-row
// stats via warp shuffles, no extra smem.
__global__ __launch_bounds__(256) void k_ffn2(const float* __restrict__ E,
                                              const float* __restrict__ W2,
                                              const float* __restrict__ b2,
                                              const float* __restrict__ ln_g,
                                              const float* __restrict__ ln_b,
                                              const float* __restrict__ gate_w,
                                              const float* __restrict__ gate_b) {
  __shared__ __align__(16) float As[16][68];
  __shared__ __align__(16) float Bs[16][260];
  const int tid = threadIdx.x;
  const int tx = tid & 31, ty = tid >> 5;
  const int row0 = blockIdx.x * 64;

  float acc[8][8];
#pragma unroll
  for (int i = 0; i < 8; i++)
#pragma unroll
    for (int j = 0; j < 8; j++) acc[i][j] = 0.f;

  for (int k0 = 0; k0 < FDIM; k0 += 16) {
    {  // A tile: 64 x 16 (256 float4, 1 per thread), transposed
      int r = tid >> 2;
      int kq = (tid & 3) << 2;
      int grow = row0 + r;
      float4 v = make_float4(0.f, 0.f, 0.f, 0.f);
      if (grow < VOCAB) v = *(const float4*)(g_t1 + (size_t)grow * FDIM + k0 + kq);
      As[kq + 0][r] = v.x; As[kq + 1][r] = v.y; As[kq + 2][r] = v.z; As[kq + 3][r] = v.w;
    }
#pragma unroll
    for (int l = 0; l < 4; l++) {  // B tile: 16 x 256
      int f = tid + l * 256;
      int r = f >> 6;
      int nq = (f & 63) << 2;
      *(float4*)&Bs[r][nq] = *(const float4*)(W2 + (size_t)(k0 + r) * HDIM + nq);
    }
    __syncthreads();
#pragma unroll
    for (int k = 0; k < 16; k++) {
      float a[8], bv[8];
      *(float4*)&a[0]  = *(const float4*)&As[k][ty * 8];
      *(float4*)&a[4]  = *(const float4*)&As[k][ty * 8 + 4];
      *(float4*)&bv[0] = *(const float4*)&Bs[k][tx * 8];
      *(float4*)&bv[4] = *(const float4*)&Bs[k][tx * 8 + 4];
#pragma unroll
      for (int i = 0; i < 8; i++)
#pragma unroll
        for (int j = 0; j < 8; j++) acc[i][j] = fmaf(a[i], bv[j], acc[i][j]);
    }
    __syncthreads();
  }

  // ---- fused epilogue: residual + LayerNorm + gate score ----
  const int c0 = tx * 8;
  float b2v[8], lg[8], lb[8], gw[8], gg[8];
  *(float4*)&b2v[0] = *(const float4*)(b2 + c0);     *(float4*)&b2v[4] = *(const float4*)(b2 + c0 + 4);
  *(float4*)&lg[0]  = *(const float4*)(ln_g + c0);   *(float4*)&lg[4]  = *(const float4*)(ln_g + c0 + 4);
  *(float4*)&lb[0]  = *(const float4*)(ln_b + c0);   *(float4*)&lb[4]  = *(const float4*)(ln_b + c0 + 4);
  *(float4*)&gw[0]  = *(const float4*)(gate_w + c0); *(float4*)&gw[4]  = *(const float4*)(gate_w + c0 + 4);
  float s1 = 0.f, s2 = 0.f;
#pragma unroll
  for (int j = 0; j < 8; j++) { gg[j] = lg[j] * gw[j]; s1 += gg[j]; s2 += lb[j] * gw[j]; }
  s1 = wred_sum(s1);
  s2 = wred_sum(s2);
  const float gb = gate_b[0];

#pragma unroll
  for (int i = 0; i < 8; i++) {
    int grow = row0 + ty * 8 + i;
    if (grow >= VOCAB) continue;  // uniform across warp: all lanes share grow
    float hv[8];
    *(float4*)&hv[0] = *(const float4*)(E + (size_t)grow * HDIM + c0);
    *(float4*)&hv[4] = *(const float4*)(E + (size_t)grow * HDIM + c0 + 4);
    float x[8];
    float ps = 0.f, ps2 = 0.f, pg = 0.f;
#pragma unroll
    for (int j = 0; j < 8; j++) {
      x[j] = acc[i][j] + b2v[j] + hv[j];
      ps += x[j]; ps2 += x[j] * x[j]; pg += x[j] * gg[j];
    }
    ps = wred_sum(ps); ps2 = wred_sum(ps2); pg = wred_sum(pg);
    float mu  = ps * (1.f / 256.f);
    float var = ps2 * (1.f / 256.f) - mu * mu;
    float rsig = 1.f / sqrtf(var + 1e-5f);
    if (tx == 0) g_score[grow] = rsig * (pg - mu * s1) + s2 + gb;
    float o[8];
#pragma unroll
    for (int j = 0; j < 8; j++) o[j] = (x[j] - mu) * rsig * lg[j] + lb[j];
    *(float4*)(g_hidden + (size_t)grow * HDIM + c0)     = *(float4*)&o[0];
    *(float4*)(g_hidden + (size_t)grow * HDIM + c0 + 4) = *(float4*)&o[4];
  }
}

// ---------------- Pass 3: per-batch top-512 of 4093 gathered scores (bitonic sort 4096) ----------------
__global__ __launch_bounds__(1024) void k_topk(const int* __restrict__ seq) {
  __shared__ float sv[4096];
  __shared__ int   si[4096];
  const int b = blockIdx.x;
  const int tid = threadIdx.x;

  for (int i = tid; i < 4096; i += 1024) {
    if (i < TCAND) {
      int tok = seq[b * SEQT + i];
      sv[i] = g_score[tok];
      si[i] = i;
    } else {
      sv[i] = -INFINITY;
      si[i] = i;
    }
  }
  __syncthreads();

  for (int k = 2; k <= 4096; k <<= 1) {
    for (int j = k >> 1; j > 0; j >>= 1) {
      for (int t = tid; t < 2048; t += 1024) {
        int i = ((t & ~(j - 1)) << 1) | (t & (j - 1));
        int p = i | j;
        float v1 = sv[i], v2 = sv[p];
        int i1 = si[i], i2 = si[p];
        // "v1 ranks before v2" in descending order (ties: smaller index first)
        bool gt = (v1 > v2) || (v1 == v2 && i1 < i2);
        bool desc = ((i & k) == 0);
        if (desc ? !gt : gt) { sv[i] = v2; sv[p] = v1; si[i] = i2; si[p] = i1; }
      }
      __syncthreads();
    }
  }
  // top 512 positions -> store the token ids (row content is all that matters)
  for (int m = tid; m < MSEL; m += 1024) g_mem_tok[b * MSEL + m] = seq[b * SEQT + si[m]];
}

// ---------------- Pass 4: query projection + attention + context, one block per batch ----------------
__global__ __launch_bounds__(256) void k_attn(const int* __restrict__ seq,
                                              const float* __restrict__ qa_w,
                                              const float* __restrict__ qa_b,
                                              const float* __restrict__ qr_w,
                                              const float* __restrict__ qr_b) {
  __shared__ float hq[HDIM], q1[HDIM], q2[HDIM];
  __shared__ float att[MSEL];
  __shared__ int   stok[MSEL];
  __shared__ float red[8];
  const int b = blockIdx.x;
  const int tid = threadIdx.x;
  const int lane = tid & 31, w = tid >> 5;

  int tokq = seq[b * SEQT + (SEQT - 2)];
  hq[tid] = g_hidden[(size_t)tokq * HDIM + tid];
  for (int m = tid; m < MSEL; m += 256) stok[m] = g_mem_tok[b * MSEL + m];
  __syncthreads();

  float a = qa_b[tid];
  for (int h = 0; h < HDIM; h++) a = fmaf(hq[h], qa_w[h * HDIM + tid], a);
  q1[tid] = a;
  __syncthreads();
  a = qr_b[tid];
  for (int h = 0; h < HDIM; h++) a = fmaf(q1[h], qr_w[h * HDIM + tid], a);
  q2[tid] = a;
  __syncthreads();

  // att[m] = memory[m] . q  (one warp per m)
  for (int m = w; m < MSEL; m += 8) {
    const float* row = g_hidden + (size_t)stok[m] * HDIM;
    float s = 0.f;
#pragma unroll
    for (int c = 0; c < 8; c++) s = fmaf(row[lane + 32 * c], q2[lane + 32 * c], s);
    s = wred_sum(s);
    if (lane == 0) att[m] = s;
  }
  __syncthreads();

  // softmax (max-subtracted)
  float mx = fmaxf(att[tid], att[tid + 256]);
#pragma unroll
  for (int o = 16; o > 0; o >>= 1) mx = fmaxf(mx, __shfl_xor_sync(0xffffffffu, mx, o));
  if (lane == 0) red[w] = mx;
  __syncthreads();
  float gmx = red[0];
#pragma unroll
  for (int i = 1; i < 8; i++) gmx = fmaxf(gmx, red[i]);
  float e0 = expf(att[tid] - gmx);
  float e1 = expf(att[tid + 256] - gmx);
  float sm = wred_sum(e0 + e1);
  __syncthreads();  // all reads of red done
  if (lane == 0) red[w] = sm;
  att[tid] = e0;
  att[tid + 256] = e1;
  __syncthreads();
  float S = 0.f;
#pragma unroll
  for (int i = 0; i < 8; i++) S += red[i];
  float inv = 1.f / S;

  // ctx[h] = (1/S) * sum_m e[m] * memory[m][h]
  float c = 0.f;
  for (int m = 0; m < MSEL; m++) c = fmaf(att[m], g_hidden[(size_t)stok[m] * HDIM + tid], c);
  g_ctx[b * HDIM + tid] = c * inv;
}

// ---------------- Pass 5: out = ctx @ out_w + out_b, (16,256)x(256,50257) ----------------
__global__ __launch_bounds__(256) void k_out(const float* __restrict__ Wo,
                                             const float* __restrict__ bo,
                                             float* __restrict__ out) {
  __shared__ float cs[NBATCH * HDIM];
  const int tid = threadIdx.x;
  for (int i = tid; i < NBATCH * HDIM; i += 256) cs[i] = g_ctx[i];
  __syncthreads();
  int v = blockIdx.x * 256 + tid;
  if (v >= VOCAB) return;
  float accv[NBATCH];
  float bias = bo[v];
#pragma unroll
  for (int b = 0; b < NBATCH; b++) accv[b] = bias;
#pragma unroll 8
  for (int h = 0; h < HDIM; h++) {
    float wv = Wo[(size_t)h * VOCAB + v];
#pragma unroll
    for (int b = 0; b < NBATCH; b++) accv[b] = fmaf(cs[b * HDIM + h], wv, accv[b]);
  }
#pragma unroll
  for (int b = 0; b < NBATCH; b++) out[(size_t)b * VOCAB + v] = accv[b];
}

// ---------------- launch ----------------
extern "C" void kernel_launch(void* const* d_in, const int* in_sizes, int n_in,
                              void* d_out, int out_size) {
  const int*   seq    = (const int*)  d_in[0];
  const float* embed  = (const float*)d_in[1];
  const float* W1     = (const float*)d_in[2];
  const float* b1     = (const float*)d_in[3];
  const float* W2     = (const float*)d_in[4];
  const float* b2     = (const float*)d_in[5];
  const float* ln_g   = (const float*)d_in[6];
  const float* ln_b   = (const float*)d_in[7];
  const float* gate_w = (const float*)d_in[8];
  const float* gate_b = (const float*)d_in[9];
  const float* qa_w   = (const float*)d_in[10];
  const float* qa_b   = (const float*)d_in[11];
  const float* qr_w   = (const float*)d_in[12];
  const float* qr_b   = (const float*)d_in[13];
  const float* out_w  = (const float*)d_in[14];
  const float* out_b  = (const float*)d_in[15];
  float* out = (float*)d_out;

  dim3 g1((VOCAB + 127) / 128, FDIM / 128);
  k_ffn1<<<g1, 256>>>(embed, W1, b1);
  k_ffn2<<<(VOCAB + 63) / 64, 256>>>(embed, W2, b2, ln_g, ln_b, gate_w, gate_b);
  k_topk<<<NBATCH, 1024>>>(seq);
  k_attn<<<NBATCH, 256>>>(seq, qa_w, qa_b, qr_w, qr_b);
  k_out<<<(VOCAB + 255) / 256, 256>>>(out_w, out_b, out);
}